// round 2
// baseline (speedup 1.0000x reference)
#include <cuda_runtime.h>
#include <cuda_bf16.h>
#include <math.h>

#define N_NODES 100000
#define N_EDGES 1000000
#define C 64          // channels (IN_CH == HID == 64)
#define C4 16         // float4 chunks per row

// ---------------- scratch (device globals; no allocation allowed) -----------
__device__ __align__(16) float g_agg[(size_t)N_NODES * C];
__device__ __align__(16) float g_h1 [(size_t)N_NODES * C];
__device__ __align__(16) float g_h2 [(size_t)N_NODES * C];
__device__ __align__(16) float g_cnt[N_NODES];
__device__ __align__(16) float g_inv[N_NODES];

// ---------------- f32x2 packed FMA helpers ----------------------------------
__device__ __forceinline__ unsigned long long pk2(float lo, float hi) {
    unsigned long long r;
    asm("mov.b64 %0, {%1, %2};" : "=l"(r) : "f"(lo), "f"(hi));
    return r;
}
__device__ __forceinline__ unsigned long long fma2(unsigned long long a,
                                                   unsigned long long b,
                                                   unsigned long long c) {
    unsigned long long d;
    asm("fma.rn.f32x2 %0, %1, %2, %3;" : "=l"(d) : "l"(a), "l"(b), "l"(c));
    return d;
}
__device__ __forceinline__ void unpk2(unsigned long long v, float& lo, float& hi) {
    asm("mov.b64 {%0, %1}, %2;" : "=f"(lo), "=f"(hi) : "l"(v));
}

// ---------------- zero agg (and optionally cnt) ------------------------------
// grid: 6250 x 256 threads = 1.6M threads = N_NODES*C/4 float4s
template <bool ZERO_CNT>
__global__ void zero_kernel() {
    int idx = blockIdx.x * blockDim.x + threadIdx.x;
    float4 z = make_float4(0.f, 0.f, 0.f, 0.f);
    ((float4*)g_agg)[idx] = z;
    if (ZERO_CNT && idx < N_NODES / 4) {
        ((float4*)g_cnt)[idx] = z;
    }
}

// ---------------- degree count ------------------------------------------------
__global__ void degree_kernel(const int* __restrict__ dst) {
    int e = blockIdx.x * blockDim.x + threadIdx.x;
    if (e < N_EDGES) {
        atomicAdd(&g_cnt[dst[e]], 1.0f);   // emitted as RED (no return use)
    }
}

__global__ void inv_kernel() {
    int i = blockIdx.x * blockDim.x + threadIdx.x;
    if (i < N_NODES) {
        g_inv[i] = 1.0f / fmaxf(g_cnt[i], 1.0f);
    }
}

// ---------------- edge scatter: agg[dst] += feat[src] ------------------------
// 16 threads per edge, one float4 chunk each. Gather and RED are both
// coalesced 256B row accesses; data is L2-resident.
__global__ void scatter_kernel(const float* __restrict__ x_ext,
                               const int* __restrict__ src,
                               const int* __restrict__ dst,
                               int layer) {
    unsigned idx = blockIdx.x * blockDim.x + threadIdx.x;   // < E*16
    int e = idx >> 4;
    int c = idx & 15;
    const float* feat = (layer == 0) ? x_ext : g_h1;
    int s = src[e];
    int d = dst[e];
    float4 v = ((const float4*)feat)[s * C4 + c];
    float* p = &g_agg[(size_t)d * C + c * 4];
    asm volatile("red.global.add.v4.f32 [%0], {%1,%2,%3,%4};"
                 :: "l"(p), "f"(v.x), "f"(v.y), "f"(v.z), "f"(v.w)
                 : "memory");
}

// ---------------- node update: out = relu(mean @ Wl^T + b + self @ Wr^T) -----
// block = 256 threads, 16 nodes per block (N_NODES % 16 == 0 -> 6250 blocks).
// thread t: node = t/16, output quad o4 = t%16 (outputs o4*4 .. o4*4+3).
// W stored transposed [k][o] with row pad 68 (16B-aligned rows, no bank dup).
__global__ void __launch_bounds__(256) sage_node_kernel(
        const float* __restrict__ x_ext,
        const float* __restrict__ Wl,
        const float* __restrict__ bias,
        const float* __restrict__ Wr,
        int layer) {
    __shared__ float sWl[C * 68];
    __shared__ float sWr[C * 68];
    __shared__ float sMean[16 * 68];
    __shared__ float sSelf[16 * 68];
    __shared__ float sB[C];

    const float* self_feat = (layer == 0) ? x_ext : g_h1;
    float* out = (layer == 0) ? g_h1 : g_h2;

    int t = threadIdx.x;
    int nodeBase = blockIdx.x * 16;

    // stage W transposed: sW[k*68 + o] = W[o*64 + k]
    #pragma unroll 4
    for (int i = t; i < C * C; i += 256) {
        int o = i >> 6, k = i & 63;
        sWl[k * 68 + o] = Wl[i];
        sWr[k * 68 + o] = Wr[i];
    }
    if (t < C) sB[t] = bias[t];

    // stage 16 nodes of mean + self (float4, coalesced)
    {
        int node = t >> 4;          // 0..15
        int c    = t & 15;          // float4 chunk
        int gn = nodeBase + node;
        float inv = g_inv[gn];
        float4 a = ((const float4*)g_agg)[gn * C4 + c];
        a.x *= inv; a.y *= inv; a.z *= inv; a.w *= inv;
        *(float4*)&sMean[node * 68 + c * 4] = a;
        float4 s4 = ((const float4*)self_feat)[gn * C4 + c];
        *(float4*)&sSelf[node * 68 + c * 4] = s4;
    }
    __syncthreads();

    int node = t >> 4;
    int o4   = t & 15;
    int gn = nodeBase + node;

    unsigned long long acc01 = pk2(sB[o4 * 4 + 0], sB[o4 * 4 + 1]);
    unsigned long long acc23 = pk2(sB[o4 * 4 + 2], sB[o4 * 4 + 3]);

    const float* mrow = &sMean[node * 68];
    const float* srow = &sSelf[node * 68];

    #pragma unroll 16
    for (int k = 0; k < C; k++) {
        float mk = mrow[k];
        float sk = srow[k];
        unsigned long long mk2 = pk2(mk, mk);
        unsigned long long sk2 = pk2(sk, sk);
        float4 wl = *(const float4*)&sWl[k * 68 + o4 * 4];
        float4 wr = *(const float4*)&sWr[k * 68 + o4 * 4];
        acc01 = fma2(mk2, pk2(wl.x, wl.y), acc01);
        acc23 = fma2(mk2, pk2(wl.z, wl.w), acc23);
        acc01 = fma2(sk2, pk2(wr.x, wr.y), acc01);
        acc23 = fma2(sk2, pk2(wr.z, wr.w), acc23);
    }

    float4 r;
    unpk2(acc01, r.x, r.y);
    unpk2(acc23, r.z, r.w);
    r.x = fmaxf(r.x, 0.f);
    r.y = fmaxf(r.y, 0.f);
    r.z = fmaxf(r.z, 0.f);
    r.w = fmaxf(r.w, 0.f);
    ((float4*)out)[gn * C4 + o4] = r;
}

// ---------------- output head: sigmoid(h2 @ w_out^T + b_out) -----------------
// 256 threads -> 64 nodes/block; 4 threads per node, shuffle-reduce.
__global__ void out_kernel(const float* __restrict__ w_out,
                           const float* __restrict__ b_out,
                           float* __restrict__ out) {
    __shared__ float sw[C];
    if (threadIdx.x < C) sw[threadIdx.x] = w_out[threadIdx.x];
    __syncthreads();

    int node = blockIdx.x * 64 + (threadIdx.x >> 2);
    int q = threadIdx.x & 3;
    bool valid = node < N_NODES;
    int n = valid ? node : (N_NODES - 1);     // clamp so all lanes stay active

    float acc = 0.f;
    const float4* row = (const float4*)(g_h2 + (size_t)n * C);
    const float4* wv  = (const float4*)sw;
    #pragma unroll
    for (int i = 0; i < 4; i++) {
        float4 v = row[q * 4 + i];
        float4 w = wv[q * 4 + i];
        acc += v.x * w.x + v.y * w.y + v.z * w.z + v.w * w.w;
    }
    acc += __shfl_down_sync(0xffffffffu, acc, 2);
    acc += __shfl_down_sync(0xffffffffu, acc, 1);
    if (q == 0 && valid) {
        float logit = acc + b_out[0];
        out[node] = 1.0f / (1.0f + expf(-logit));
    }
}

// ---------------- launch -----------------------------------------------------
extern "C" void kernel_launch(void* const* d_in, const int* in_sizes, int n_in,
                              void* d_out, int out_size) {
    const float* x     = (const float*)d_in[0];
    const int*   ei    = (const int*)  d_in[1];
    const float* w1_l  = (const float*)d_in[2];
    const float* b1    = (const float*)d_in[3];
    const float* w1_r  = (const float*)d_in[4];
    const float* w2_l  = (const float*)d_in[5];
    const float* b2    = (const float*)d_in[6];
    const float* w2_r  = (const float*)d_in[7];
    const float* w_out = (const float*)d_in[8];
    const float* b_out = (const float*)d_in[9];
    float* out = (float*)d_out;

    const int* src = ei;            // edge_index[0]
    const int* dst = ei + N_EDGES;  // edge_index[1]

    const int ZB = (N_NODES * C / 4) / 256;           // 6250
    const int SB = (N_EDGES * 16) / 256;              // 62500
    const int NB = N_NODES / 16;                      // 6250

    // degree + inverse (same for both layers)
    zero_kernel<true><<<ZB, 256>>>();
    degree_kernel<<<(N_EDGES + 255) / 256, 256>>>(dst);
    inv_kernel<<<(N_NODES + 255) / 256, 256>>>();

    // layer 1
    scatter_kernel<<<SB, 256>>>(x, src, dst, 0);
    sage_node_kernel<<<NB, 256>>>(x, w1_l, b1, w1_r, 0);

    // layer 2
    zero_kernel<false><<<ZB, 256>>>();
    scatter_kernel<<<SB, 256>>>(x, src, dst, 1);
    sage_node_kernel<<<NB, 256>>>(x, w2_l, b2, w2_r, 1);

    // head
    out_kernel<<<(N_NODES + 63) / 64, 256>>>(w_out, b_out, out);
}

// round 4
// speedup vs baseline: 2.9673x; 2.9673x over previous
#include <cuda_runtime.h>
#include <math.h>

#define N_NODES 100000
#define N_EDGES 1000000
#define C 64
#define N_PAD 100032            // 1563 * 64
#define SCAN_BLOCKS 98          // 98*1024 >= N_NODES

typedef unsigned long long ull;

// ---------------- scratch (device globals; no allocation allowed) -----------
__device__ __align__(16) float g_mean[(size_t)N_PAD * C];
__device__ __align__(16) float g_h1  [(size_t)N_PAD * C];
__device__ int g_deg[N_NODES];
__device__ int g_inc[SCAN_BLOCKS * 1024];
__device__ int g_rowptr[N_NODES + 1];
__device__ int g_cursor[N_NODES];
__device__ int g_col[N_EDGES];
__device__ int g_bsum[128];
__device__ int g_boff[128];

// ---------------- f32x2 packed FMA helpers ----------------------------------
__device__ __forceinline__ ull pk2(float lo, float hi) {
    ull r;
    asm("mov.b64 %0, {%1, %2};" : "=l"(r) : "f"(lo), "f"(hi));
    return r;
}
__device__ __forceinline__ ull fma2(ull a, ull b, ull c) {
    ull d;
    asm("fma.rn.f32x2 %0, %1, %2, %3;" : "=l"(d) : "l"(a), "l"(b), "l"(c));
    return d;
}
__device__ __forceinline__ void unpk2(ull v, float& lo, float& hi) {
    asm("mov.b64 {%0, %1}, %2;" : "=f"(lo), "=f"(hi) : "l"(v));
}

// ========================= CSR build =========================================
__global__ void zero_deg_kernel() {
    int i = blockIdx.x * 1024 + threadIdx.x;
    if (i < N_NODES) g_deg[i] = 0;
}

__global__ void deg_kernel(const int* __restrict__ dst) {
    int e = blockIdx.x * blockDim.x + threadIdx.x;
    if (e < N_EDGES) atomicAdd(&g_deg[dst[e]], 1);
}

__global__ void scan1_kernel() {
    __shared__ int s[1024];
    int t = threadIdx.x;
    int i = blockIdx.x * 1024 + t;
    int v = (i < N_NODES) ? g_deg[i] : 0;
    s[t] = v;
    __syncthreads();
    for (int off = 1; off < 1024; off <<= 1) {
        int a = (t >= off) ? s[t - off] : 0;
        __syncthreads();
        s[t] += a;
        __syncthreads();
    }
    if (i < N_NODES) g_inc[i] = s[t];
    if (t == 1023) g_bsum[blockIdx.x] = s[1023];
}

__global__ void scan2_kernel() {
    __shared__ int s[128];
    int t = threadIdx.x;
    int v = (t < SCAN_BLOCKS) ? g_bsum[t] : 0;
    s[t] = v;
    __syncthreads();
    for (int off = 1; off < 128; off <<= 1) {
        int a = (t >= off) ? s[t - off] : 0;
        __syncthreads();
        s[t] += a;
        __syncthreads();
    }
    g_boff[t] = s[t] - v;   // exclusive
}

__global__ void scan3_kernel() {
    int t = threadIdx.x;
    int i = blockIdx.x * 1024 + t;
    if (i < N_NODES) {
        int val = g_inc[i] + g_boff[blockIdx.x];
        g_rowptr[i + 1] = val;
        g_cursor[i] = val - g_deg[i];
        if (i == 0) g_rowptr[0] = 0;
    }
}

__global__ void fill_kernel(const int* __restrict__ src, const int* __restrict__ dst) {
    int e = blockIdx.x * blockDim.x + threadIdx.x;
    if (e < N_EDGES) {
        int pos = atomicAdd(&g_cursor[dst[e]], 1);
        g_col[pos] = src[e];
    }
}

// ========================= mean aggregation ==================================
// 16 threads per node (one float4 chunk each). Pure gather over CSR; writes
// the normalized mean directly. LAYER selects the feature source INSIDE device
// code (device globals must never be passed as args from host).
template <int LAYER>
__global__ void __launch_bounds__(256) agg_mean_kernel(const float* __restrict__ x_ext) {
    int idx = blockIdx.x * 256 + threadIdx.x;
    int n = idx >> 4;
    int c = idx & 15;
    if (n >= N_NODES) {
        ((float4*)g_mean)[(size_t)n * 16 + c] = make_float4(0.f, 0.f, 0.f, 0.f);
        return;
    }
    const float* feat = (LAYER == 1) ? x_ext : (const float*)g_h1;
    int beg = g_rowptr[n];
    int end = g_rowptr[n + 1];
    const float4* f4 = (const float4*)feat;
    float4 acc = make_float4(0.f, 0.f, 0.f, 0.f);
    int j = beg;
    for (; j + 1 < end; j += 2) {
        int s0 = g_col[j];
        int s1 = g_col[j + 1];
        float4 a = f4[(size_t)s0 * 16 + c];
        float4 b = f4[(size_t)s1 * 16 + c];
        acc.x += a.x + b.x; acc.y += a.y + b.y;
        acc.z += a.z + b.z; acc.w += a.w + b.w;
    }
    if (j < end) {
        int s0 = g_col[j];
        float4 a = f4[(size_t)s0 * 16 + c];
        acc.x += a.x; acc.y += a.y; acc.z += a.z; acc.w += a.w;
    }
    float inv = 1.0f / fmaxf((float)(end - beg), 1.0f);
    acc.x *= inv; acc.y *= inv; acc.z *= inv; acc.w *= inv;
    ((float4*)g_mean)[(size_t)n * 16 + c] = acc;
}

// ========================= node GEMM =========================================
// 64 nodes/block, 128 threads. Thread t: og = t&15 (outputs 4*og..4*og+3),
// ng = t>>4 (nodes 8*ng..8*ng+7). Mean/self stored DUPLICATED as (v,v) u64 in
// shared; weights transposed so LDS.128 yields output pairs.
// LAYER==2 reads self from g_h1 (device-side) and fuses the sigmoid head.
#define SW_STRIDE 68            // floats per weight row (16B aligned)
#define SM_STRIDE 65            // u64 per node row
#define SMEM_BYTES (2*64*SW_STRIDE*4 + 2*64*SM_STRIDE*8)   // 101376

template <int LAYER>
__global__ void __launch_bounds__(128) node_kernel(
        const float* __restrict__ x_ext,
        const float* __restrict__ Wl,
        const float* __restrict__ bias,
        const float* __restrict__ Wr,
        const float* __restrict__ w_out,
        const float* __restrict__ b_out,
        float* __restrict__ out) {
    extern __shared__ char smraw[];
    float* sWl = (float*)smraw;                       // [64][SW_STRIDE]
    float* sWr = sWl + 64 * SW_STRIDE;
    ull* sMd = (ull*)(sWr + 64 * SW_STRIDE);          // [64][SM_STRIDE] dup pairs
    ull* sSd = sMd + 64 * SM_STRIDE;

    const float* selfF = (LAYER == 1) ? x_ext : (const float*)g_h1;

    int t = threadIdx.x;
    int og = t & 15;
    int ng = t >> 4;
    int base = blockIdx.x * 64;

    // stage weights transposed: sW[k*STRIDE + o] = W[o*64 + k]
    #pragma unroll
    for (int i = t; i < 64 * 64; i += 128) {
        int o = i >> 6, k = i & 63;
        sWl[k * SW_STRIDE + o] = Wl[i];
        sWr[k * SW_STRIDE + o] = Wr[i];
    }

    // stage mean/self duplicated: sMd[n*STRIDE + k] = (v, v)
    #pragma unroll
    for (int it = 0; it < 8; ++it) {
        int item = it * 128 + t;
        int n = item & 63;
        int c = item >> 6;                           // float4 chunk 0..15
        int gn = base + n;
        int cn = (LAYER == 1) ? min(gn, N_NODES - 1) : gn;  // x is unpadded
        float4 m = ((const float4*)g_mean)[(size_t)gn * 16 + c];
        float4 s = ((const float4*)selfF)[(size_t)cn * 16 + c];
        ull* mp = &sMd[n * SM_STRIDE + 4 * c];
        ull* sp = &sSd[n * SM_STRIDE + 4 * c];
        mp[0] = pk2(m.x, m.x); mp[1] = pk2(m.y, m.y);
        mp[2] = pk2(m.z, m.z); mp[3] = pk2(m.w, m.w);
        sp[0] = pk2(s.x, s.x); sp[1] = pk2(s.y, s.y);
        sp[2] = pk2(s.z, s.z); sp[3] = pk2(s.w, s.w);
    }
    __syncthreads();

    float4 b4 = *(const float4*)&bias[og * 4];
    ull acc[8][2];
    #pragma unroll
    for (int n = 0; n < 8; ++n) {
        acc[n][0] = pk2(b4.x, b4.y);
        acc[n][1] = pk2(b4.z, b4.w);
    }

    const ull* mrow = &sMd[(ng * 8) * SM_STRIDE];
    const ull* srow = &sSd[(ng * 8) * SM_STRIDE];

    #pragma unroll 4
    for (int k = 0; k < C; ++k) {
        ulonglong2 wl = *(const ulonglong2*)&sWl[k * SW_STRIDE + og * 4];
        ulonglong2 wr = *(const ulonglong2*)&sWr[k * SW_STRIDE + og * 4];
        ull mv[8], sv[8];
        #pragma unroll
        for (int n = 0; n < 8; ++n) {
            mv[n] = mrow[n * SM_STRIDE + k];
            sv[n] = srow[n * SM_STRIDE + k];
        }
        // batch mean-terms then self-terms: >=16-op reuse distance per acc
        #pragma unroll
        for (int n = 0; n < 8; ++n) {
            acc[n][0] = fma2(mv[n], wl.x, acc[n][0]);
            acc[n][1] = fma2(mv[n], wl.y, acc[n][1]);
        }
        #pragma unroll
        for (int n = 0; n < 8; ++n) {
            acc[n][0] = fma2(sv[n], wr.x, acc[n][0]);
            acc[n][1] = fma2(sv[n], wr.y, acc[n][1]);
        }
    }

    if (LAYER == 1) {
        #pragma unroll
        for (int n = 0; n < 8; ++n) {
            float4 r;
            unpk2(acc[n][0], r.x, r.y);
            unpk2(acc[n][1], r.z, r.w);
            r.x = fmaxf(r.x, 0.f); r.y = fmaxf(r.y, 0.f);
            r.z = fmaxf(r.z, 0.f); r.w = fmaxf(r.w, 0.f);
            int gn = base + ng * 8 + n;
            ((float4*)g_h1)[(size_t)gn * 16 + og] = r;   // gn < N_PAD
        }
    } else {
        float4 wo = *(const float4*)&w_out[og * 4];
        float bo = b_out[0];
        #pragma unroll
        for (int n = 0; n < 8; ++n) {
            float r0, r1, r2, r3;
            unpk2(acc[n][0], r0, r1);
            unpk2(acc[n][1], r2, r3);
            r0 = fmaxf(r0, 0.f); r1 = fmaxf(r1, 0.f);
            r2 = fmaxf(r2, 0.f); r3 = fmaxf(r3, 0.f);
            float p = r0 * wo.x + r1 * wo.y + r2 * wo.z + r3 * wo.w;
            // reduce over the 16 og lanes (xor 1,2,4,8 stays within og group)
            p += __shfl_xor_sync(0xffffffffu, p, 1);
            p += __shfl_xor_sync(0xffffffffu, p, 2);
            p += __shfl_xor_sync(0xffffffffu, p, 4);
            p += __shfl_xor_sync(0xffffffffu, p, 8);
            if (og == 0) {
                int gn = base + ng * 8 + n;
                if (gn < N_NODES) {
                    out[gn] = 1.0f / (1.0f + expf(-(p + bo)));
                }
            }
        }
    }
}

// ========================= launch ============================================
extern "C" void kernel_launch(void* const* d_in, const int* in_sizes, int n_in,
                              void* d_out, int out_size) {
    const float* x     = (const float*)d_in[0];
    const int*   ei    = (const int*)  d_in[1];
    const float* w1_l  = (const float*)d_in[2];
    const float* b1    = (const float*)d_in[3];
    const float* w1_r  = (const float*)d_in[4];
    const float* w2_l  = (const float*)d_in[5];
    const float* b2    = (const float*)d_in[6];
    const float* w2_r  = (const float*)d_in[7];
    const float* w_out = (const float*)d_in[8];
    const float* b_out = (const float*)d_in[9];
    float* out = (float*)d_out;

    const int* src = ei;
    const int* dst = ei + N_EDGES;

    cudaFuncSetAttribute(node_kernel<1>, cudaFuncAttributeMaxDynamicSharedMemorySize, SMEM_BYTES);
    cudaFuncSetAttribute(node_kernel<2>, cudaFuncAttributeMaxDynamicSharedMemorySize, SMEM_BYTES);

    const int EB = (N_EDGES + 255) / 256;      // 3907
    const int AB = (N_PAD * 16) / 256;         // 6252
    const int NB = N_PAD / 64;                 // 1563

    // ---- CSR build (per call; edge_index is an input) ----
    zero_deg_kernel<<<SCAN_BLOCKS, 1024>>>();
    deg_kernel<<<EB, 256>>>(dst);
    scan1_kernel<<<SCAN_BLOCKS, 1024>>>();
    scan2_kernel<<<1, 128>>>();
    scan3_kernel<<<SCAN_BLOCKS, 1024>>>();
    fill_kernel<<<EB, 256>>>(src, dst);

    // ---- layer 1 ----
    agg_mean_kernel<1><<<AB, 256>>>(x);
    node_kernel<1><<<NB, 128, SMEM_BYTES>>>(x, w1_l, b1, w1_r, w_out, b_out, out);

    // ---- layer 2 (+ fused sigmoid head) ----
    agg_mean_kernel<2><<<AB, 256>>>(x);
    node_kernel<2><<<NB, 128, SMEM_BYTES>>>(x, w2_l, b2, w2_r, w_out, b_out, out);
}